// round 4
// baseline (speedup 1.0000x reference)
#include <cuda_runtime.h>

// Problem constants
#define Bc 4
#define Sc 2048
#define Hc 1024
#define Ec 8
#define Kc 2
#define Tc (Bc * Sc)          // 8192 tokens
#define Pc (Tc * Kc)          // 16384 (token, expert) pairs
#define TILE_M 128
#define MAX_ROWS (Pc + Ec * TILE_M)   // 17408 (worst-case per-expert padding)
#define MAX_TILES (MAX_ROWS / TILE_M) // 136

// ---------------------------------------------------------------------------
// Scratch (device globals -- no runtime allocation allowed)
// ---------------------------------------------------------------------------
__device__ int g_is64;                 // 1 if top_k_index is int64, else 0
__device__ int g_counts[Ec];
__device__ int g_cursor[Ec];
__device__ int g_expert_off[Ec];
__device__ int g_tile_expert[MAX_TILES];
__device__ int g_slot_token[MAX_ROWS];
__device__ int g_pair_slot[Pc];
__device__ __align__(16) float g_h1[(size_t)MAX_ROWS * Hc]; // ~71 MB
__device__ __align__(16) float g_y [(size_t)MAX_ROWS * Hc]; // ~71 MB

// Read pair p's expert id under either dtype layout.
__device__ __forceinline__ int load_expert(const int* idx, int p, int is64) {
    // int64 little-endian: value word at 2*p; int32: word at p.
    return idx[is64 ? (p << 1) : p] & (Ec - 1);
}

// ---------------------------------------------------------------------------
// K-1: dtype detection, strictly in-bounds under BOTH interpretations.
// Probe words idx[2p+1] for p < Pc/2 (max word index Pc-1 = 16383, always
// within the 16384-int32 minimum buffer). If data is int64 with values 0..7,
// all probed (high) words are 0. If data is int32, the probed words are
// uniform 0..7 -> P(all 8192 zero) = 8^-8192 ~ 0.
// ---------------------------------------------------------------------------
__global__ void detect_kernel(const int* __restrict__ idx) {
    __shared__ int any_nonzero;
    if (threadIdx.x == 0) any_nonzero = 0;
    __syncthreads();
    int found = 0;
    for (int p = threadIdx.x; p < Pc / 2; p += blockDim.x)
        if (idx[2 * p + 1] != 0) found = 1;
    if (found) atomicExch(&any_nonzero, 1);
    __syncthreads();
    if (threadIdx.x == 0) g_is64 = any_nonzero ? 0 : 1;
}

// K0: init counters + padding sentinels
__global__ void init_kernel() {
    int i = blockIdx.x * blockDim.x + threadIdx.x;
    if (i < MAX_ROWS) g_slot_token[i] = -1;
    if (i < Ec) { g_counts[i] = 0; g_cursor[i] = 0; }
}

// K1: histogram of pairs per expert
__global__ void hist_kernel(const int* __restrict__ idx) {
    int p = blockIdx.x * blockDim.x + threadIdx.x;
    if (p < Pc) atomicAdd(&g_counts[load_expert(idx, p, g_is64)], 1);
}

// K2: tile-aligned exclusive scan + tile->expert map (tiny, 1 thread)
__global__ void scan_kernel() {
    if (threadIdx.x == 0 && blockIdx.x == 0) {
        int off = 0;
        for (int e = 0; e < Ec; e++) {
            g_expert_off[e] = off;
            int nt = (g_counts[e] + TILE_M - 1) / TILE_M;
            for (int i = 0; i < nt; i++) g_tile_expert[off / TILE_M + i] = e;
            off += nt * TILE_M;
        }
        for (int t = off / TILE_M; t < MAX_TILES; t++) g_tile_expert[t] = 0;
    }
}

// K3: place each pair into its expert's slot range
__global__ void place_kernel(const int* __restrict__ idx) {
    int p = blockIdx.x * blockDim.x + threadIdx.x;
    if (p < Pc) {
        int e = load_expert(idx, p, g_is64);
        int pos = atomicAdd(&g_cursor[e], 1);
        int slot = g_expert_off[e] + pos;
        g_slot_token[slot] = p >> 1;   // p / Kc
        g_pair_slot[p] = slot;
    }
}

// ---------------------------------------------------------------------------
// Grouped SGEMM: 128x128 tile, BK=16, 256 threads, 8x8 register blocking.
// FIRST=true : A = gathered hidden rows, epilogue relu(acc + b1), out = g_h1
// FIRST=false: A = g_h1 rows (dense),    epilogue acc + b2,       out = g_y
// ---------------------------------------------------------------------------
template <bool FIRST>
__global__ __launch_bounds__(256, 2)
void gemm_kernel(const float* __restrict__ X,     // hidden (only used if FIRST)
                 const float* __restrict__ W,     // (E, H, H) row-major per expert
                 const float* __restrict__ bias)  // (E, H)
{
    __shared__ __align__(16) float As[16][TILE_M];
    __shared__ __align__(16) float Bs[16][128];

    const int tile = blockIdx.x;
    const int n0   = blockIdx.y * 128;
    const int e    = g_tile_expert[tile];
    const float* Wt = W + (size_t)e * Hc * Hc;

    const int tid = threadIdx.x;
    const int tx = tid & 15;        // col group (8 cols)
    const int ty = tid >> 4;        // row group (8 rows)

    // A-load assignment: 2 float4 per thread (512 float4 total).
    const int rowA0 = tid >> 2;         // 0..63
    const int rowA1 = rowA0 + 64;       // 64..127
    const int kq    = (tid & 3) * 4;    // k offset within BK=16

    const float* aSrc0;
    const float* aSrc1;
    if (FIRST) {
        int t0 = g_slot_token[tile * TILE_M + rowA0];
        int t1 = g_slot_token[tile * TILE_M + rowA1];
        aSrc0 = (t0 >= 0) ? X + (size_t)t0 * Hc : nullptr;
        aSrc1 = (t1 >= 0) ? X + (size_t)t1 * Hc : nullptr;
    } else {
        aSrc0 = g_h1 + (size_t)(tile * TILE_M + rowA0) * Hc;
        aSrc1 = g_h1 + (size_t)(tile * TILE_M + rowA1) * Hc;
    }

    // B-load assignment: 2 float4 per thread.
    const int kb0 = tid >> 5;           // 0..7
    const int kb1 = kb0 + 8;            // 8..15
    const int nb  = (tid & 31) * 4;     // 0..124

    float acc[8][8];
    #pragma unroll
    for (int i = 0; i < 8; i++)
        #pragma unroll
        for (int j = 0; j < 8; j++) acc[i][j] = 0.f;

    for (int k0 = 0; k0 < Hc; k0 += 16) {
        float4 av0 = aSrc0 ? *(const float4*)(aSrc0 + k0 + kq) : make_float4(0.f, 0.f, 0.f, 0.f);
        float4 av1 = aSrc1 ? *(const float4*)(aSrc1 + k0 + kq) : make_float4(0.f, 0.f, 0.f, 0.f);
        float4 bv0 = *(const float4*)(Wt + (size_t)(k0 + kb0) * Hc + n0 + nb);
        float4 bv1 = *(const float4*)(Wt + (size_t)(k0 + kb1) * Hc + n0 + nb);

        __syncthreads();   // previous iteration's reads complete
        As[kq + 0][rowA0] = av0.x;  As[kq + 1][rowA0] = av0.y;
        As[kq + 2][rowA0] = av0.z;  As[kq + 3][rowA0] = av0.w;
        As[kq + 0][rowA1] = av1.x;  As[kq + 1][rowA1] = av1.y;
        As[kq + 2][rowA1] = av1.z;  As[kq + 3][rowA1] = av1.w;
        *(float4*)&Bs[kb0][nb] = bv0;
        *(float4*)&Bs[kb1][nb] = bv1;
        __syncthreads();

        #pragma unroll
        for (int kk = 0; kk < 16; kk++) {
            float a[8], b[8];
            *(float4*)&a[0] = *(const float4*)&As[kk][ty * 8];
            *(float4*)&a[4] = *(const float4*)&As[kk][ty * 8 + 4];
            *(float4*)&b[0] = *(const float4*)&Bs[kk][tx * 8];
            *(float4*)&b[4] = *(const float4*)&Bs[kk][tx * 8 + 4];
            #pragma unroll
            for (int i = 0; i < 8; i++)
                #pragma unroll
                for (int j = 0; j < 8; j++)
                    acc[i][j] += a[i] * b[j];
        }
    }

    // Epilogue
    float bb[8];
    #pragma unroll
    for (int j = 0; j < 8; j++) bb[j] = bias[e * Hc + n0 + tx * 8 + j];

    float* Obase = FIRST ? g_h1 : g_y;
    #pragma unroll
    for (int i = 0; i < 8; i++) {
        float v[8];
        #pragma unroll
        for (int j = 0; j < 8; j++) {
            float x = acc[i][j] + bb[j];
            if (FIRST) x = fmaxf(x, 0.f);
            v[j] = x;
        }
        float* op = Obase + (size_t)(tile * TILE_M + ty * 8 + i) * Hc + n0 + tx * 8;
        *(float4*)op       = *(float4*)&v[0];
        *(float4*)(op + 4) = *(float4*)&v[4];
    }
}

// ---------------------------------------------------------------------------
// K6: deterministic combine  out[t] = w0 * y[slot0] + w1 * y[slot1]
// ---------------------------------------------------------------------------
__global__ void combine_kernel(const float* __restrict__ tkw,
                               float* __restrict__ out)
{
    int gid = blockIdx.x * blockDim.x + threadIdx.x;   // over Tc * (Hc/4)
    if (gid < Tc * (Hc / 4)) {
        int t  = gid >> 8;          // Hc/4 = 256 float4 per token
        int h4 = gid & 255;
        float w0 = tkw[2 * t];
        float w1 = tkw[2 * t + 1];
        int   s0 = g_pair_slot[2 * t];
        int   s1 = g_pair_slot[2 * t + 1];
        const float4* y4 = (const float4*)g_y;
        float4 a = y4[(size_t)s0 * (Hc / 4) + h4];
        float4 b = y4[(size_t)s1 * (Hc / 4) + h4];
        float4 r;
        r.x = w0 * a.x + w1 * b.x;
        r.y = w0 * a.y + w1 * b.y;
        r.z = w0 * a.z + w1 * b.z;
        r.w = w0 * a.w + w1 * b.w;
        ((float4*)out)[gid] = r;
    }
}

// ---------------------------------------------------------------------------
extern "C" void kernel_launch(void* const* d_in, const int* in_sizes, int n_in,
                              void* d_out, int out_size)
{
    const float* hidden = (const float*)d_in[0];
    const int*   tk_idx = (const int*)d_in[1];     // int32 OR int64 (detected)
    const float* tk_w   = (const float*)d_in[2];
    const float* w1     = (const float*)d_in[3];
    const float* b1     = (const float*)d_in[4];
    const float* w2     = (const float*)d_in[5];
    const float* b2     = (const float*)d_in[6];
    float*       out    = (float*)d_out;

    detect_kernel<<<1, 256>>>(tk_idx);
    init_kernel <<<(MAX_ROWS + 255) / 256, 256>>>();
    hist_kernel <<<(Pc + 255) / 256, 256>>>(tk_idx);
    scan_kernel <<<1, 32>>>();
    place_kernel<<<(Pc + 255) / 256, 256>>>(tk_idx);

    dim3 gg(MAX_TILES, Hc / 128);
    gemm_kernel<true >  <<<gg, 256>>>(hidden, w1, b1);
    gemm_kernel<false>  <<<gg, 256>>>(nullptr, w2, b2);

    combine_kernel<<<(Tc * (Hc / 4) + 255) / 256, 256>>>(tk_w, out);
}

// round 13
// speedup vs baseline: 2.6725x; 2.6725x over previous
#include <cuda_runtime.h>
#include <cstdint>

// Problem constants
#define Bc 4
#define Sc 2048
#define Hc 1024
#define Ec 8
#define Kc 2
#define Tc (Bc * Sc)          // 8192 tokens
#define Pc (Tc * Kc)          // 16384 pairs
#define TILE_M 128
#define MAX_ROWS (Pc + Ec * TILE_M)   // 17408
#define MAX_TILES (MAX_ROWS / TILE_M) // 136

// GEMM tiling: CTA 128x64, BK=32, single 24KB smem buffer, reg prefetch
#define BM 128
#define BN 64
#define BK 32
#define NITER (Hc / BK)              // 32
#define NTHREADS 256
#define A_FLOATS (BM * BK)           // 4096
#define B_FLOATS (BK * BN)           // 2048
#define STAGE_FLOATS (A_FLOATS + B_FLOATS)   // 6144 floats = 24 KB

// ---------------------------------------------------------------------------
// Scratch — EXACTLY the Round-4-proven global footprint (142.6 MB total).
// No g_xr / g_w1r / g_w2r: tf32 rounding happens in the GEMM store phase.
// ---------------------------------------------------------------------------
__device__ int g_is64;
__device__ int g_counts[Ec];
__device__ int g_cursor[Ec];
__device__ int g_expert_off[Ec];
__device__ int g_tile_expert[MAX_TILES];
__device__ int g_slot_token[MAX_ROWS];
__device__ int g_pair_slot[Pc];
__device__ __align__(16) float g_h1[(size_t)MAX_ROWS * Hc];
__device__ __align__(16) float g_y [(size_t)MAX_ROWS * Hc];

// ---------------------------------------------------------------------------
// Helpers (sm_100 baseline; no tcgen05, no cp.async)
// ---------------------------------------------------------------------------
__device__ __forceinline__ float tf32_rn(float x) {
    uint32_t u;
    asm("cvt.rna.tf32.f32 %0, %1;" : "=r"(u) : "f"(x));
    return __uint_as_float(u);
}
__device__ __forceinline__ float4 tf32_rn4(float4 v) {
    v.x = tf32_rn(v.x); v.y = tf32_rn(v.y);
    v.z = tf32_rn(v.z); v.w = tf32_rn(v.w);
    return v;
}

#define MMA_TF32(d, a, b0, b1) \
    asm volatile("mma.sync.aligned.m16n8k8.row.col.f32.tf32.tf32.f32 " \
                 "{%0,%1,%2,%3}, {%4,%5,%6,%7}, {%8,%9}, {%0,%1,%2,%3};" \
                 : "+f"((d)[0]), "+f"((d)[1]), "+f"((d)[2]), "+f"((d)[3]) \
                 : "r"((a)[0]), "r"((a)[1]), "r"((a)[2]), "r"((a)[3]), \
                   "r"(b0), "r"(b1))

// ---------------------------------------------------------------------------
// Routing prologue (validated in Round 4)
// ---------------------------------------------------------------------------
__global__ void detect_kernel(const int* __restrict__ idx) {
    __shared__ int any_nonzero;
    if (threadIdx.x == 0) any_nonzero = 0;
    __syncthreads();
    int found = 0;
    for (int p = threadIdx.x; p < Pc / 2; p += blockDim.x)
        if (idx[2 * p + 1] != 0) found = 1;
    if (found) atomicExch(&any_nonzero, 1);
    __syncthreads();
    if (threadIdx.x == 0) g_is64 = any_nonzero ? 0 : 1;
}
__device__ __forceinline__ int load_expert(const int* idx, int p, int is64) {
    return idx[is64 ? (p << 1) : p] & (Ec - 1);
}
__global__ void init_kernel() {
    int i = blockIdx.x * blockDim.x + threadIdx.x;
    if (i < MAX_ROWS) g_slot_token[i] = -1;
    if (i < Ec) { g_counts[i] = 0; g_cursor[i] = 0; }
}
__global__ void hist_kernel(const int* __restrict__ idx) {
    int p = blockIdx.x * blockDim.x + threadIdx.x;
    if (p < Pc) atomicAdd(&g_counts[load_expert(idx, p, g_is64)], 1);
}
__global__ void scan_kernel() {
    if (threadIdx.x == 0 && blockIdx.x == 0) {
        int off = 0;
        for (int e = 0; e < Ec; e++) {
            g_expert_off[e] = off;
            int nt = (g_counts[e] + TILE_M - 1) / TILE_M;
            for (int i = 0; i < nt; i++) g_tile_expert[off / TILE_M + i] = e;
            off += nt * TILE_M;
        }
        for (int t = off / TILE_M; t < MAX_TILES; t++) g_tile_expert[t] = 0;
    }
}
__global__ void place_kernel(const int* __restrict__ idx) {
    int p = blockIdx.x * blockDim.x + threadIdx.x;
    if (p < Pc) {
        int e = load_expert(idx, p, g_is64);
        int pos = atomicAdd(&g_cursor[e], 1);
        int slot = g_expert_off[e] + pos;
        g_slot_token[slot] = p >> 1;
        g_pair_slot[p] = slot;
    }
}

// ---------------------------------------------------------------------------
// TF32 tensor-core FFN pass. CTA 128x64, BK=32, 256 threads,
// 8 warps (4 m x 2 n), warp tile 32x32 -> acc 32 floats/thread.
// Plain LDG float4 -> tf32 RNA round in registers -> STS (no cp.async).
// SMEM swizzle:  A phys = m*32 + (k ^ (4*(m&7)))     [128 x 32]
//                B phys = k*64  + (n ^ (8*(k&7)))    [32 x 64]
// Store phases and all fragment reads are bank-conflict-free.
// FIRST: A = gathered hidden rows (raw fp32, rounded here), out = g_h1
// else : A = g_h1 (already rounded),                        out = g_y
// ---------------------------------------------------------------------------
template <bool FIRST>
__global__ __launch_bounds__(NTHREADS)
void ffn_kernel(const float* __restrict__ X,     // hidden (FIRST) / unused
                const float* __restrict__ W,     // raw w1 or w2 (E,H,H)
                const float* __restrict__ bias)
{
    __shared__ __align__(16) float smem[STAGE_FLOATS];   // 24 KB

    const int tid  = threadIdx.x;
    const int wid  = tid >> 5;
    const int lane = tid & 31;
    const int tile = blockIdx.x;
    const int n0   = blockIdx.y * BN;
    const int e    = g_tile_expert[tile];

    const int wm = (wid & 3) * 32;       // warp m offset (4 warps)
    const int wn = (wid >> 2) * 32;      // warp n offset (2 warps)
    const int r  = lane >> 2;            // 0..7 (groupID)
    const int cc = lane & 3;             // 0..3 (threadID in group)
    const int fourR = 4 * r;

    const float* __restrict__ wexp = W + ((size_t)e << 20);

    // ---- per-thread load/store assignments: A 4x16B, B 2x16B per iter ----
    const float* pA[4]; float* dA[4];
    #pragma unroll
    for (int s = 0; s < 4; s++) {
        int idx = s * NTHREADS + tid;          // 0..1023 A 16B-chunks
        int m = idx >> 3, k4 = idx & 7;
        dA[s] = &smem[m * 32 + ((k4 * 4) ^ (4 * (m & 7)))];
        if (FIRST) {
            int t = g_slot_token[tile * TILE_M + m];
            // padded rows (t<0): read token-0 data; those rows are never consumed
            pA[s] = (t >= 0 ? X + ((size_t)t << 10) : X) + k4 * 4;
        } else {
            pA[s] = g_h1 + (((size_t)(tile * TILE_M + m)) << 10) + k4 * 4;
        }
    }
    const float* pB[2]; float* dB[2];
    #pragma unroll
    for (int s = 0; s < 2; s++) {
        int idx = s * NTHREADS + tid;          // 0..511 B 16B-chunks
        int k = idx >> 4, nn4 = idx & 15;
        dB[s] = &smem[A_FLOATS + k * 64 + ((nn4 * 4) ^ (8 * (k & 7)))];
        pB[s] = wexp + ((size_t)k << 10) + n0 + nn4 * 4;
    }

    // ---- accumulators: 2 m-frags x 4 n-frags x 4 = 32 regs ----
    float acc[2][4][4];
    #pragma unroll
    for (int mf = 0; mf < 2; mf++)
        #pragma unroll
        for (int f = 0; f < 4; f++)
            #pragma unroll
            for (int q = 0; q < 4; q++) acc[mf][f][q] = 0.f;

    // ---- prefetch iter 0 into registers ----
    float4 va[4], vb[2];
    #pragma unroll
    for (int s = 0; s < 4; s++) { va[s] = *(const float4*)pA[s]; pA[s] += BK; }
    #pragma unroll
    for (int s = 0; s < 2; s++) { vb[s] = *(const float4*)pB[s]; pB[s] += (size_t)BK << 10; }

    #pragma unroll 1
    for (int it = 0; it < NITER; it++) {
        __syncthreads();   // previous compute done; smem reusable
        #pragma unroll
        for (int s = 0; s < 4; s++) *(float4*)dA[s] = tf32_rn4(va[s]);
        #pragma unroll
        for (int s = 0; s < 2; s++) *(float4*)dB[s] = tf32_rn4(vb[s]);
        __syncthreads();

        if (it + 1 < NITER) {   // issue next iter's loads before compute
            #pragma unroll
            for (int s = 0; s < 4; s++) { va[s] = *(const float4*)pA[s]; pA[s] += BK; }
            #pragma unroll
            for (int s = 0; s < 2; s++) { vb[s] = *(const float4*)pB[s]; pB[s] += (size_t)BK << 10; }
        }

        const uint32_t* sA = (const uint32_t*)smem;
        const uint32_t* sB = sA + A_FLOATS;

        #pragma unroll
        for (int ks = 0; ks < 4; ks++) {
            const int k0 = ks * 8 + cc;
            const int k1 = k0 + 4;
            const int ka0 = k0 ^ fourR;
            const int ka1 = k1 ^ fourR;

            uint32_t a[2][4];
            #pragma unroll
            for (int mf = 0; mf < 2; mf++) {
                int mA = (wm + mf * 16 + r) * 32;
                a[mf][0] = sA[mA + ka0];
                a[mf][1] = sA[mA + 8 * 32 + ka0];
                a[mf][2] = sA[mA + ka1];
                a[mf][3] = sA[mA + 8 * 32 + ka1];
            }

            const int rowb0 = k0 * 64, xb0 = 8 * cc;        // k0 & 7 == cc
            const int rowb1 = k1 * 64, xb1 = 8 * (cc + 4);  // k1 & 7 == cc+4
            const int nbase = wn + r;
            #pragma unroll
            for (int f = 0; f < 4; f++) {
                uint32_t b0 = sB[rowb0 + ((nbase + f * 8) ^ xb0)];
                uint32_t b1 = sB[rowb1 + ((nbase + f * 8) ^ xb1)];
                #pragma unroll
                for (int mf = 0; mf < 2; mf++)
                    MMA_TF32(acc[mf][f], a[mf], b0, b1);
            }
        }
    }

    // ---- epilogue ----
    const float* bexp = bias + e * Hc + n0 + wn;
    float* obase = FIRST ? g_h1 : g_y;
    const int c2 = cc * 2;
    #pragma unroll
    for (int mf = 0; mf < 2; mf++) {
        size_t row0 = (size_t)(tile * TILE_M + wm + mf * 16 + r);
        float* o0 = obase + (row0 << 10) + n0 + wn;
        float* o1 = o0 + (8 << 10);
        #pragma unroll
        for (int f = 0; f < 4; f++) {
            float2 bb = *(const float2*)(bexp + f * 8 + c2);
            float2 vt, vbo;
            vt.x  = acc[mf][f][0] + bb.x;  vt.y  = acc[mf][f][1] + bb.y;
            vbo.x = acc[mf][f][2] + bb.x;  vbo.y = acc[mf][f][3] + bb.y;
            if (FIRST) {
                vt.x  = tf32_rn(fmaxf(vt.x, 0.f));  vt.y  = tf32_rn(fmaxf(vt.y, 0.f));
                vbo.x = tf32_rn(fmaxf(vbo.x, 0.f)); vbo.y = tf32_rn(fmaxf(vbo.y, 0.f));
            }
            *(float2*)(o0 + f * 8 + c2) = vt;
            *(float2*)(o1 + f * 8 + c2) = vbo;
        }
    }
}

// ---------------------------------------------------------------------------
// Combine: out[t] = w0 * y[slot0] + w1 * y[slot1]
// ---------------------------------------------------------------------------
__global__ void combine_kernel(const float* __restrict__ tkw,
                               float* __restrict__ out)
{
    int gid = blockIdx.x * blockDim.x + threadIdx.x;
    if (gid < Tc * (Hc / 4)) {
        int t = gid >> 8;
        int h4 = gid & 255;
        float w0 = tkw[2 * t];
        float w1 = tkw[2 * t + 1];
        int s0 = g_pair_slot[2 * t];
        int s1 = g_pair_slot[2 * t + 1];
        const float4* y4 = (const float4*)g_y;
        float4 a = y4[(size_t)s0 * (Hc / 4) + h4];
        float4 b = y4[(size_t)s1 * (Hc / 4) + h4];
        float4 rr;
        rr.x = w0 * a.x + w1 * b.x;
        rr.y = w0 * a.y + w1 * b.y;
        rr.z = w0 * a.z + w1 * b.z;
        rr.w = w0 * a.w + w1 * b.w;
        ((float4*)out)[gid] = rr;
    }
}

// ---------------------------------------------------------------------------
extern "C" void kernel_launch(void* const* d_in, const int* in_sizes, int n_in,
                              void* d_out, int out_size)
{
    const float* hidden = (const float*)d_in[0];
    const int*   tk_idx = (const int*)d_in[1];
    const float* tk_w   = (const float*)d_in[2];
    const float* w1     = (const float*)d_in[3];
    const float* b1     = (const float*)d_in[4];
    const float* w2     = (const float*)d_in[5];
    const float* b2     = (const float*)d_in[6];
    float*       out    = (float*)d_out;

    detect_kernel<<<1, 256>>>(tk_idx);
    init_kernel <<<(MAX_ROWS + 255) / 256, 256>>>();
    hist_kernel <<<(Pc + 255) / 256, 256>>>(tk_idx);
    scan_kernel <<<1, 32>>>();
    place_kernel<<<(Pc + 255) / 256, 256>>>(tk_idx);

    dim3 gg(MAX_TILES, Hc / BN);
    ffn_kernel<true > <<<gg, NTHREADS>>>(hidden, w1, b1);
    ffn_kernel<false> <<<gg, NTHREADS>>>(nullptr, w2, b2);

    combine_kernel<<<(Tc * (Hc / 4) + 255) / 256, 256>>>(tk_w, out);
}

// round 16
// speedup vs baseline: 2.8594x; 1.0699x over previous
#include <cuda_runtime.h>
#include <cstdint>

// Problem constants
#define Bc 4
#define Sc 2048
#define Hc 1024
#define Ec 8
#define Kc 2
#define Tc (Bc * Sc)          // 8192 tokens
#define Pc (Tc * Kc)          // 16384 pairs
#define TILE_M 128
#define MAX_ROWS (Pc + Ec * TILE_M)   // 17408
#define MAX_TILES (MAX_ROWS / TILE_M) // 136

// GEMM tiling: CTA 128x128, BK=32, single 32KB smem buffer, reg prefetch
#define BM 128
#define BN 128
#define BK 32
#define NITER (Hc / BK)              // 32
#define NTHREADS 256
#define A_FLOATS (BM * BK)           // 4096
#define B_FLOATS (BK * BN)           // 4096
#define STAGE_FLOATS (A_FLOATS + B_FLOATS)   // 8192 floats = 32 KB

// ---------------------------------------------------------------------------
// Scratch — EXACTLY the Round-4/13-proven global footprint (142.6 MB total).
// (Going beyond it overflows the driver's module arena -> 128 MiB delta ->
//  harness violation. Confirmed R13.)
// ---------------------------------------------------------------------------
__device__ int g_is64;
__device__ int g_counts[Ec];
__device__ int g_cursor[Ec];
__device__ int g_expert_off[Ec];
__device__ int g_tile_expert[MAX_TILES];
__device__ int g_slot_token[MAX_ROWS];
__device__ int g_pair_slot[Pc];
__device__ __align__(16) float g_h1[(size_t)MAX_ROWS * Hc];
__device__ __align__(16) float g_y [(size_t)MAX_ROWS * Hc];

// ---------------------------------------------------------------------------
// Helpers (sm_100 baseline; no tcgen05, no cp.async)
// ---------------------------------------------------------------------------
__device__ __forceinline__ float tf32_rn(float x) {
    uint32_t u;
    asm("cvt.rna.tf32.f32 %0, %1;" : "=r"(u) : "f"(x));
    return __uint_as_float(u);
}
__device__ __forceinline__ float4 tf32_rn4(float4 v) {
    v.x = tf32_rn(v.x); v.y = tf32_rn(v.y);
    v.z = tf32_rn(v.z); v.w = tf32_rn(v.w);
    return v;
}

#define MMA_TF32(d, a, b0, b1) \
    asm volatile("mma.sync.aligned.m16n8k8.row.col.f32.tf32.tf32.f32 " \
                 "{%0,%1,%2,%3}, {%4,%5,%6,%7}, {%8,%9}, {%0,%1,%2,%3};" \
                 : "+f"((d)[0]), "+f"((d)[1]), "+f"((d)[2]), "+f"((d)[3]) \
                 : "r"((a)[0]), "r"((a)[1]), "r"((a)[2]), "r"((a)[3]), \
                   "r"(b0), "r"(b1))

// ---------------------------------------------------------------------------
// Routing prologue (validated in Round 4)
// ---------------------------------------------------------------------------
__global__ void detect_kernel(const int* __restrict__ idx) {
    __shared__ int any_nonzero;
    if (threadIdx.x == 0) any_nonzero = 0;
    __syncthreads();
    int found = 0;
    for (int p = threadIdx.x; p < Pc / 2; p += blockDim.x)
        if (idx[2 * p + 1] != 0) found = 1;
    if (found) atomicExch(&any_nonzero, 1);
    __syncthreads();
    if (threadIdx.x == 0) g_is64 = any_nonzero ? 0 : 1;
}
__device__ __forceinline__ int load_expert(const int* idx, int p, int is64) {
    return idx[is64 ? (p << 1) : p] & (Ec - 1);
}
__global__ void init_kernel() {
    int i = blockIdx.x * blockDim.x + threadIdx.x;
    if (i < MAX_ROWS) g_slot_token[i] = -1;
    if (i < Ec) { g_counts[i] = 0; g_cursor[i] = 0; }
}
__global__ void hist_kernel(const int* __restrict__ idx) {
    int p = blockIdx.x * blockDim.x + threadIdx.x;
    if (p < Pc) atomicAdd(&g_counts[load_expert(idx, p, g_is64)], 1);
}
__global__ void scan_kernel() {
    if (threadIdx.x == 0 && blockIdx.x == 0) {
        int off = 0;
        for (int e = 0; e < Ec; e++) {
            g_expert_off[e] = off;
            int nt = (g_counts[e] + TILE_M - 1) / TILE_M;
            for (int i = 0; i < nt; i++) g_tile_expert[off / TILE_M + i] = e;
            off += nt * TILE_M;
        }
        for (int t = off / TILE_M; t < MAX_TILES; t++) g_tile_expert[t] = 0;
    }
}
__global__ void place_kernel(const int* __restrict__ idx) {
    int p = blockIdx.x * blockDim.x + threadIdx.x;
    if (p < Pc) {
        int e = load_expert(idx, p, g_is64);
        int pos = atomicAdd(&g_cursor[e], 1);
        int slot = g_expert_off[e] + pos;
        g_slot_token[slot] = p >> 1;
        g_pair_slot[p] = slot;
    }
}

// ---------------------------------------------------------------------------
// TF32 tensor-core FFN pass. CTA 128x128, BK=32, 256 threads,
// 8 warps (2 m x 4 n), warp tile 64x32 -> acc 64 floats/thread.
// Plain LDG float4 -> tf32 RNA round in registers -> STS (no cp.async).
// SMEM swizzle:  A phys = m*32  + (k ^ (4*(m&7)))    [128 x 32]  (R13-proven)
//                B phys = k*128 + (n ^ (8*(k&7)))    [32 x 128]
// Store phases and all fragment reads are bank-conflict-free (verified).
// FIRST: A = gathered hidden rows (raw fp32, rounded here), out = g_h1
// else : A = g_h1 (already rounded),                        out = g_y
// ---------------------------------------------------------------------------
template <bool FIRST>
__global__ __launch_bounds__(NTHREADS)
void ffn_kernel(const float* __restrict__ X,     // hidden (FIRST) / unused
                const float* __restrict__ W,     // raw w1 or w2 (E,H,H)
                const float* __restrict__ bias)
{
    __shared__ __align__(16) float smem[STAGE_FLOATS];   // 32 KB

    const int tid  = threadIdx.x;
    const int wid  = tid >> 5;
    const int lane = tid & 31;
    const int tile = blockIdx.x;
    const int n0   = blockIdx.y * BN;
    const int e    = g_tile_expert[tile];

    const int wm = (wid & 1) * 64;       // warp m offset (2 warps)
    const int wn = (wid >> 1) * 32;      // warp n offset (4 warps)
    const int r  = lane >> 2;            // 0..7 (groupID)
    const int cc = lane & 3;             // 0..3 (threadID in group)
    const int fourR = 4 * r;

    const float* __restrict__ wexp = W + ((size_t)e << 20);

    // ---- per-thread load/store assignments: A 4x16B, B 4x16B per iter ----
    const float* pA[4]; float* dA[4];
    #pragma unroll
    for (int s = 0; s < 4; s++) {
        int idx = s * NTHREADS + tid;          // 0..1023 A 16B-chunks
        int m = idx >> 3, k4 = idx & 7;
        dA[s] = &smem[m * 32 + ((k4 * 4) ^ (4 * (m & 7)))];
        if (FIRST) {
            int t = g_slot_token[tile * TILE_M + m];
            // padded rows (t<0): read token-0 data; those rows are never consumed
            pA[s] = (t >= 0 ? X + ((size_t)t << 10) : X) + k4 * 4;
        } else {
            pA[s] = g_h1 + (((size_t)(tile * TILE_M + m)) << 10) + k4 * 4;
        }
    }
    const float* pB[4]; float* dB[4];
    #pragma unroll
    for (int s = 0; s < 4; s++) {
        int idx = s * NTHREADS + tid;          // 0..1023 B 16B-chunks
        int k = idx >> 5, nn4 = idx & 31;
        dB[s] = &smem[A_FLOATS + k * 128 + ((nn4 * 4) ^ (8 * (k & 7)))];
        pB[s] = wexp + ((size_t)k << 10) + n0 + nn4 * 4;
    }

    // ---- accumulators: 4 m-frags x 4 n-frags x 4 = 64 regs ----
    float acc[4][4][4];
    #pragma unroll
    for (int mf = 0; mf < 4; mf++)
        #pragma unroll
        for (int f = 0; f < 4; f++)
            #pragma unroll
            for (int q = 0; q < 4; q++) acc[mf][f][q] = 0.f;

    // ---- prefetch iter 0 into registers ----
    float4 va[4], vb[4];
    #pragma unroll
    for (int s = 0; s < 4; s++) { va[s] = *(const float4*)pA[s]; pA[s] += BK; }
    #pragma unroll
    for (int s = 0; s < 4; s++) { vb[s] = *(const float4*)pB[s]; pB[s] += (size_t)BK << 10; }

    #pragma unroll 1
    for (int it = 0; it < NITER; it++) {
        __syncthreads();   // previous compute done; smem reusable
        #pragma unroll
        for (int s = 0; s < 4; s++) *(float4*)dA[s] = tf32_rn4(va[s]);
        #pragma unroll
        for (int s = 0; s < 4; s++) *(float4*)dB[s] = tf32_rn4(vb[s]);
        __syncthreads();

        if (it + 1 < NITER) {   // issue next iter's loads before compute
            #pragma unroll
            for (int s = 0; s < 4; s++) { va[s] = *(const float4*)pA[s]; pA[s] += BK; }
            #pragma unroll
            for (int s = 0; s < 4; s++) { vb[s] = *(const float4*)pB[s]; pB[s] += (size_t)BK << 10; }
        }

        const uint32_t* sA = (const uint32_t*)smem;
        const uint32_t* sB = sA + A_FLOATS;

        #pragma unroll
        for (int ks = 0; ks < 4; ks++) {
            const int k0 = ks * 8 + cc;
            const int k1 = k0 + 4;
            const int ka0 = k0 ^ fourR;
            const int ka1 = k1 ^ fourR;

            uint32_t a[4][4];
            #pragma unroll
            for (int mf = 0; mf < 4; mf++) {
                int mA = (wm + mf * 16 + r) * 32;
                a[mf][0] = sA[mA + ka0];
                a[mf][1] = sA[mA + 8 * 32 + ka0];
                a[mf][2] = sA[mA + ka1];
                a[mf][3] = sA[mA + 8 * 32 + ka1];
            }

            const int rowb0 = k0 * 128, xb0 = 8 * cc;        // k0 & 7 == cc
            const int rowb1 = k1 * 128, xb1 = 8 * (cc + 4);  // k1 & 7 == cc+4
            const int nbase = wn + r;
            #pragma unroll
            for (int f = 0; f < 4; f++) {
                uint32_t b0 = sB[rowb0 + ((nbase + f * 8) ^ xb0)];
                uint32_t b1 = sB[rowb1 + ((nbase + f * 8) ^ xb1)];
                #pragma unroll
                for (int mf = 0; mf < 4; mf++)
                    MMA_TF32(acc[mf][f], a[mf], b0, b1);
            }
        }
    }

    // ---- epilogue ----
    const float* bexp = bias + e * Hc + n0 + wn;
    float* obase = FIRST ? g_h1 : g_y;
    const int c2 = cc * 2;
    #pragma unroll
    for (int mf = 0; mf < 4; mf++) {
        size_t row0 = (size_t)(tile * TILE_M + wm + mf * 16 + r);
        float* o0 = obase + (row0 << 10) + n0 + wn;
        float* o1 = o0 + (8 << 10);
        #pragma unroll
        for (int f = 0; f < 4; f++) {
            float2 bb = *(const float2*)(bexp + f * 8 + c2);
            float2 vt, vbo;
            vt.x  = acc[mf][f][0] + bb.x;  vt.y  = acc[mf][f][1] + bb.y;
            vbo.x = acc[mf][f][2] + bb.x;  vbo.y = acc[mf][f][3] + bb.y;
            if (FIRST) {
                vt.x  = tf32_rn(fmaxf(vt.x, 0.f));  vt.y  = tf32_rn(fmaxf(vt.y, 0.f));
                vbo.x = tf32_rn(fmaxf(vbo.x, 0.f)); vbo.y = tf32_rn(fmaxf(vbo.y, 0.f));
            }
            *(float2*)(o0 + f * 8 + c2) = vt;
            *(float2*)(o1 + f * 8 + c2) = vbo;
        }
    }
}

// ---------------------------------------------------------------------------
// Combine: out[t] = w0 * y[slot0] + w1 * y[slot1]
// ---------------------------------------------------------------------------
__global__ void combine_kernel(const float* __restrict__ tkw,
                               float* __restrict__ out)
{
    int gid = blockIdx.x * blockDim.x + threadIdx.x;
    if (gid < Tc * (Hc / 4)) {
        int t = gid >> 8;
        int h4 = gid & 255;
        float w0 = tkw[2 * t];
        float w1 = tkw[2 * t + 1];
        int s0 = g_pair_slot[2 * t];
        int s1 = g_pair_slot[2 * t + 1];
        const float4* y4 = (const float4*)g_y;
        float4 a = y4[(size_t)s0 * (Hc / 4) + h4];
        float4 b = y4[(size_t)s1 * (Hc / 4) + h4];
        float4 rr;
        rr.x = w0 * a.x + w1 * b.x;
        rr.y = w0 * a.y + w1 * b.y;
        rr.z = w0 * a.z + w1 * b.z;
        rr.w = w0 * a.w + w1 * b.w;
        ((float4*)out)[gid] = rr;
    }
}

// ---------------------------------------------------------------------------
extern "C" void kernel_launch(void* const* d_in, const int* in_sizes, int n_in,
                              void* d_out, int out_size)
{
    const float* hidden = (const float*)d_in[0];
    const int*   tk_idx = (const int*)d_in[1];
    const float* tk_w   = (const float*)d_in[2];
    const float* w1     = (const float*)d_in[3];
    const float* b1     = (const float*)d_in[4];
    const float* w2     = (const float*)d_in[5];
    const float* b2     = (const float*)d_in[6];
    float*       out    = (float*)d_out;

    detect_kernel<<<1, 256>>>(tk_idx);
    init_kernel <<<(MAX_ROWS + 255) / 256, 256>>>();
    hist_kernel <<<(Pc + 255) / 256, 256>>>(tk_idx);
    scan_kernel <<<1, 32>>>();
    place_kernel<<<(Pc + 255) / 256, 256>>>(tk_idx);

    dim3 gg(MAX_TILES, Hc / BN);
    ffn_kernel<true > <<<gg, NTHREADS>>>(hidden, w1, b1);
    ffn_kernel<false> <<<gg, NTHREADS>>>(nullptr, w2, b2);

    combine_kernel<<<(Tc * (Hc / 4) + 255) / 256, 256>>>(tk_w, out);
}